// round 4
// baseline (speedup 1.0000x reference)
#include <cuda_runtime.h>
#include <math_constants.h>

#define NB 8
#define HW 1024

typedef unsigned long long u64;

// ---------------- scratch (no allocations allowed) ----------------
__device__ float g_qkv [NB * 192 * HW];   // [b][c][p], q scaled, bias applied
__device__ float g_attn[NB * 64  * HW];   // [b][n*8+d][p] attention output pre-projection

// ---------------- packed f32x2 helpers (sm_103a FFMA2 path) ----------------
__device__ __forceinline__ u64 pk2(float lo, float hi) {
    u64 r; asm("mov.b64 %0,{%1,%2};" : "=l"(r) : "f"(lo), "f"(hi)); return r;
}
__device__ __forceinline__ float2 upk2(u64 v) {
    float2 f; asm("mov.b64 {%0,%1},%2;" : "=f"(f.x), "=f"(f.y) : "l"(v)); return f;
}
__device__ __forceinline__ u64 fma2(u64 a, u64 b, u64 c) {
    u64 r; asm("fma.rn.f32x2 %0,%1,%2,%3;" : "=l"(r) : "l"(a), "l"(b), "l"(c)); return r;
}
__device__ __forceinline__ u64 add2(u64 a, u64 b) {
    u64 r; asm("add.rn.f32x2 %0,%1,%2;" : "=l"(r) : "l"(a), "l"(b)); return r;
}
__device__ __forceinline__ u64 mul2(u64 a, u64 b) {
    u64 r; asm("mul.rn.f32x2 %0,%1,%2;" : "=l"(r) : "l"(a), "l"(b)); return r;
}

// ======================================================================
// 1x1 conv (GEMM): out[b][c_off+c][p] = bias[c] + sum_ic w[c][ic]*x[b][ic][p]
// Microtile 8 channels x 2 pixels per thread iteration; weights transposed
// in SMEM so channel pairs are contiguous (packed FMA b-operand).
// ======================================================================
template<int OC, bool QSCALE>
__global__ __launch_bounds__(128)
void conv1x1_kernel(const float* __restrict__ x, const float* __restrict__ w,
                    const float* __restrict__ bias, float* __restrict__ out,
                    int out_bstride, int c_off)
{
    constexpr int PT = 64;            // pixels per block
    extern __shared__ float sm[];
    float* wst = sm;                  // [64][OC] transposed weights
    float* xs  = sm + 64 * OC;        // [64][PT]

    const int tid = threadIdx.x;
    const int pt  = blockIdx.x;
    const int b   = blockIdx.y;
    const int pbase = pt * PT;

    for (int i = tid; i < OC * 64; i += 128) {
        int oc = i >> 6, ic = i & 63;
        wst[ic * OC + oc] = w[i];
    }
    for (int i = tid; i < 64 * PT; i += 128) {
        int ic = i / PT, pp = i - ic * PT;
        xs[i] = x[(b * 64 + ic) * HW + pbase + pp];
    }
    __syncthreads();

    constexpr int CG = OC / 8;
    constexpr int NM = CG * (PT / 2);
    for (int mIdx = tid; mIdx < NM; mIdx += 128) {
        int cg = mIdx >> 5;        // channel group (8 channels)
        int pg = mIdx & 31;        // pixel pair
        u64 acc[8];
        #pragma unroll
        for (int i = 0; i < 8; ++i) acc[i] = 0ull;

        #pragma unroll 8
        for (int ic = 0; ic < 64; ++ic) {
            const ulonglong2* wp = (const ulonglong2*)(wst + ic * OC + cg * 8);
            ulonglong2 w0 = wp[0], w1 = wp[1];
            float2 xv = *(const float2*)(xs + ic * PT + pg * 2);
            u64 x0 = pk2(xv.x, xv.x), x1 = pk2(xv.y, xv.y);
            acc[0] = fma2(x0, w0.x, acc[0]); acc[1] = fma2(x0, w0.y, acc[1]);
            acc[2] = fma2(x0, w1.x, acc[2]); acc[3] = fma2(x0, w1.y, acc[3]);
            acc[4] = fma2(x1, w0.x, acc[4]); acc[5] = fma2(x1, w0.y, acc[5]);
            acc[6] = fma2(x1, w1.x, acc[6]); acc[7] = fma2(x1, w1.y, acc[7]);
        }

        const int cbase = cg * 8;
        #pragma unroll
        for (int cc = 0; cc < 4; ++cc) {
            int c0 = cbase + 2 * cc;
            float b0 = bias[c0], b1 = bias[c0 + 1];
            float2 f0 = upk2(acc[cc]);       // pixel0 channels c0,c0+1
            float2 f1 = upk2(acc[cc + 4]);   // pixel1
            float v00 = f0.x + b0, v01 = f0.y + b1;
            float v10 = f1.x + b0, v11 = f1.y + b1;
            if (QSCALE && c0 < 64) {         // q channels get dkh^-0.5
                const float S = 0.35355339059327373f;
                v00 *= S; v01 *= S; v10 *= S; v11 *= S;
            }
            size_t base = (size_t)b * out_bstride + (size_t)(c_off + c0) * HW
                        + pbase + pg * 2;
            out[base]          = v00;
            out[base + HW]     = v01;
            out[base + 1]      = v10;
            out[base + HW + 1] = v11;
        }
    }
}

// ======================================================================
// Fused attention: per (b,head), queries in lanes, keys swept broadcast
// from SMEM.  logit(j) = q.k_j + rw[w2] + rh[h2], online softmax, PV.
// ======================================================================
__global__ __launch_bounds__(128)
void attn_kernel(const float* __restrict__ relw_g, const float* __restrict__ relh_g)
{
    extern __shared__ float sm[];
    float* ks  = sm;                 // [8][1024] d-major (key pairs contiguous)
    float* vs  = sm + 8192;          // [1024][8] key-major (d pairs contiguous)
    float* rws = sm + 16384;         // [63][8]
    float* rhs = sm + 16384 + 512;   // [63][8]

    const int tid  = threadIdx.x;
    const int bh   = blockIdx.y;
    const int b    = bh >> 3;
    const int head = bh & 7;

    const float* kg = g_qkv + (size_t)(b * 192 + 64 + head * 8) * HW;
    const float* vg = kg + 64 * HW;

    for (int i = tid; i < 2048; i += 128)
        ((float4*)ks)[i] = ((const float4*)kg)[i];
    for (int i = tid; i < 2048; i += 128) {
        int d = i >> 8; int j4 = (i & 255) << 2;
        float4 v = ((const float4*)(vg + d * HW))[i & 255];
        vs[(j4 + 0) * 8 + d] = v.x;
        vs[(j4 + 1) * 8 + d] = v.y;
        vs[(j4 + 2) * 8 + d] = v.z;
        vs[(j4 + 3) * 8 + d] = v.w;
    }
    for (int i = tid; i < 504; i += 128) { rws[i] = relw_g[i]; rhs[i] = relh_g[i]; }
    __syncthreads();

    const int p  = blockIdx.x * 128 + tid;   // query pixel
    const int hq = p >> 5, wq = p & 31;

    const float* qg = g_qkv + (size_t)(b * 192 + head * 8) * HW + p;
    float q[8];
    #pragma unroll
    for (int d = 0; d < 8; ++d) q[d] = qg[d * HW];
    u64 qd[8];
    #pragma unroll
    for (int d = 0; d < 8; ++d) qd[d] = pk2(q[d], q[d]);

    // rel-width table for reachable offsets, packed in registers
    u64 rw[16];
    #pragma unroll
    for (int e = 0; e < 16; ++e) {
        const float* r0 = rws + (2 * e - wq + 31) * 8;
        float a0 = 0.f, a1 = 0.f;
        #pragma unroll
        for (int d = 0; d < 8; ++d) { a0 += q[d] * r0[d]; a1 += q[d] * r0[8 + d]; }
        rw[e] = pk2(a0, a1);
    }
    // rel-height table (dynamic index in main loop -> local mem, 1 LDL / 32 keys)
    float rh[32];
    for (int e = 0; e < 32; ++e) {
        const float* r0 = rhs + (e - hq + 31) * 8;
        float a = 0.f;
        #pragma unroll
        for (int d = 0; d < 8; ++d) a += q[d] * r0[d];
        rh[e] = a;
    }

    float m = -CUDART_INF_F, s = 0.f;
    u64 o[4] = {0ull, 0ull, 0ull, 0ull};

    for (int h2 = 0; h2 < 32; ++h2) {
        float rhv = rh[h2];
        u64 rh2 = pk2(rhv, rhv);
        #pragma unroll
        for (int g = 0; g < 8; ++g) {          // 4 keys per iteration
            int j = h2 * 32 + g * 4;
            u64 l01 = add2(rh2, rw[2 * g]);
            u64 l23 = add2(rh2, rw[2 * g + 1]);
            #pragma unroll
            for (int d = 0; d < 8; ++d) {
                ulonglong2 kk = *(const ulonglong2*)(ks + d * HW + j);
                l01 = fma2(qd[d], kk.x, l01);
                l23 = fma2(qd[d], kk.y, l23);
            }
            float2 f01 = upk2(l01), f23 = upk2(l23);
            float mx = fmaxf(fmaxf(f01.x, f01.y), fmaxf(f23.x, f23.y));
            if (mx > m) {
                float c = __expf(m - mx);
                s *= c;
                u64 c2 = pk2(c, c);
                o[0] = mul2(o[0], c2); o[1] = mul2(o[1], c2);
                o[2] = mul2(o[2], c2); o[3] = mul2(o[3], c2);
                m = mx;
            }
            float p0 = __expf(f01.x - m);
            float p1 = __expf(f01.y - m);
            float p2 = __expf(f23.x - m);
            float p3 = __expf(f23.y - m);
            s += (p0 + p1) + (p2 + p3);

            const ulonglong2* vp = (const ulonglong2*)(vs + j * 8);
            ulonglong2 va, vb;
            u64 pd;
            pd = pk2(p0, p0); va = vp[0]; vb = vp[1];
            o[0] = fma2(pd, va.x, o[0]); o[1] = fma2(pd, va.y, o[1]);
            o[2] = fma2(pd, vb.x, o[2]); o[3] = fma2(pd, vb.y, o[3]);
            pd = pk2(p1, p1); va = vp[2]; vb = vp[3];
            o[0] = fma2(pd, va.x, o[0]); o[1] = fma2(pd, va.y, o[1]);
            o[2] = fma2(pd, vb.x, o[2]); o[3] = fma2(pd, vb.y, o[3]);
            pd = pk2(p2, p2); va = vp[4]; vb = vp[5];
            o[0] = fma2(pd, va.x, o[0]); o[1] = fma2(pd, va.y, o[1]);
            o[2] = fma2(pd, vb.x, o[2]); o[3] = fma2(pd, vb.y, o[3]);
            pd = pk2(p3, p3); va = vp[6]; vb = vp[7];
            o[0] = fma2(pd, va.x, o[0]); o[1] = fma2(pd, va.y, o[1]);
            o[2] = fma2(pd, vb.x, o[2]); o[3] = fma2(pd, vb.y, o[3]);
        }
    }

    float inv = 1.f / s;
    float* og = g_attn + (size_t)(b * 64 + head * 8) * HW + p;
    #pragma unroll
    for (int e = 0; e < 4; ++e) {
        float2 f = upk2(o[e]);
        og[(2 * e)     * HW] = f.x * inv;
        og[(2 * e + 1) * HW] = f.y * inv;
    }
}

// ======================================================================
// 3x3 conv, pad 1: block = (row band of 8, oc group of 16, b).
// Thread = one pixel, 16 output channels packed as 8 f32x2 accumulators.
// ======================================================================
__global__ __launch_bounds__(256)
void conv3x3_kernel(const float* __restrict__ x, const float* __restrict__ w,
                    const float* __restrict__ bias, float* __restrict__ out)
{
    __shared__ float xs[8][10][34];                  // ic-chunk x (rows+halo) x (cols+halo)
    __shared__ __align__(16) float wst[8][9][16];    // [ic][k][oc] transposed

    const int tid  = threadIdx.x;
    const int band = blockIdx.x;
    const int ocg  = blockIdx.y;
    const int b    = blockIdx.z;
    const int lr = tid >> 5, lc = tid & 31;
    const int r  = band * 8 + lr;

    u64 acc[8];
    #pragma unroll
    for (int i = 0; i < 8; ++i) acc[i] = 0ull;

    for (int cc8 = 0; cc8 < 64; cc8 += 8) {
        for (int i = tid; i < 8 * 10 * 34; i += 256) {
            int ic = i / 340; int rem = i - ic * 340;
            int rr = rem / 34; int col = rem - rr * 34;
            int gr = band * 8 - 1 + rr; int gc = col - 1;
            float v = 0.f;
            if (gr >= 0 && gr < 32 && gc >= 0 && gc < 32)
                v = x[(b * 64 + cc8 + ic) * HW + gr * 32 + gc];
            xs[ic][rr][col] = v;
        }
        for (int i = tid; i < 8 * 9 * 16; i += 256) {
            int oc = i & 15; int t = i >> 4; int k = t % 9; int ic = t / 9;
            wst[ic][k][oc] = w[((ocg * 16 + oc) * 64 + cc8 + ic) * 9 + k];
        }
        __syncthreads();

        #pragma unroll
        for (int ic = 0; ic < 8; ++ic) {
            float xv[9];
            #pragma unroll
            for (int kr = 0; kr < 3; ++kr)
                #pragma unroll
                for (int kc = 0; kc < 3; ++kc)
                    xv[kr * 3 + kc] = xs[ic][lr + kr][lc + kc];
            #pragma unroll
            for (int k = 0; k < 9; ++k) {
                u64 xd = pk2(xv[k], xv[k]);
                const ulonglong2* wp = (const ulonglong2*)&wst[ic][k][0];
                ulonglong2 wa = wp[0], wb = wp[1], wc = wp[2], wd = wp[3];
                acc[0] = fma2(xd, wa.x, acc[0]); acc[1] = fma2(xd, wa.y, acc[1]);
                acc[2] = fma2(xd, wb.x, acc[2]); acc[3] = fma2(xd, wb.y, acc[3]);
                acc[4] = fma2(xd, wc.x, acc[4]); acc[5] = fma2(xd, wc.y, acc[5]);
                acc[6] = fma2(xd, wd.x, acc[6]); acc[7] = fma2(xd, wd.y, acc[7]);
            }
        }
        __syncthreads();
    }

    #pragma unroll
    for (int i = 0; i < 8; ++i) {
        int c = ocg * 16 + 2 * i;
        float2 f = upk2(acc[i]);
        size_t base = (size_t)(b * 128 + c) * HW + r * 32 + lc;
        out[base]      = f.x + bias[c];
        out[base + HW] = f.y + bias[c + 1];
    }
}

// ======================================================================
extern "C" void kernel_launch(void* const* d_in, const int* in_sizes, int n_in,
                              void* d_out, int out_size)
{
    const float* x      = (const float*)d_in[0];
    const float* conv_w = (const float*)d_in[1];
    const float* conv_b = (const float*)d_in[2];
    const float* qkv_w  = (const float*)d_in[3];
    const float* qkv_b  = (const float*)d_in[4];
    const float* attn_w = (const float*)d_in[5];
    const float* attn_b = (const float*)d_in[6];
    const float* relw   = (const float*)d_in[7];
    const float* relh   = (const float*)d_in[8];
    float* out = (float*)d_out;

    float *qkv_buf = nullptr, *attn_buf = nullptr;
    cudaGetSymbolAddress((void**)&qkv_buf, g_qkv);
    cudaGetSymbolAddress((void**)&attn_buf, g_attn);

    cudaFuncSetAttribute((const void*)conv1x1_kernel<192, true>,
                         cudaFuncAttributeMaxDynamicSharedMemorySize, 65536);
    cudaFuncSetAttribute((const void*)attn_kernel,
                         cudaFuncAttributeMaxDynamicSharedMemorySize, 69632);

    // qkv 1x1 (q scaled) -> fused attention -> output projection; conv3x3 last
    conv1x1_kernel<192, true><<<dim3(16, 8), 128, 65536>>>(
        x, qkv_w, qkv_b, qkv_buf, 192 * HW, 0);
    attn_kernel<<<dim3(8, 64), 128, 69632>>>(relw, relh);
    conv1x1_kernel<64, false><<<dim3(16, 8), 128, 32768>>>(
        attn_buf, attn_w, attn_b, out, 128 * HW, 64);
    conv3x3_kernel<<<dim3(4, 4, 8), 256>>>(x, conv_w, conv_b, out);
}

// round 5
// speedup vs baseline: 1.4596x; 1.4596x over previous
#include <cuda_runtime.h>
#include <math_constants.h>

#define NB 8
#define HW 1024

typedef unsigned long long u64;

// ---------------- scratch (no allocations allowed) ----------------
__device__ float g_qkv [NB * 192 * HW];   // [b][c][p], q scaled, bias applied
__device__ float g_attn[NB * 64  * HW];   // [b][n*8+d][p] attention output pre-projection

// ---------------- packed f32x2 helpers (sm_103a FFMA2 path) ----------------
__device__ __forceinline__ u64 pk2(float lo, float hi) {
    u64 r; asm("mov.b64 %0,{%1,%2};" : "=l"(r) : "f"(lo), "f"(hi)); return r;
}
__device__ __forceinline__ float2 upk2(u64 v) {
    float2 f; asm("mov.b64 {%0,%1},%2;" : "=f"(f.x), "=f"(f.y) : "l"(v)); return f;
}
__device__ __forceinline__ u64 fma2(u64 a, u64 b, u64 c) {
    u64 r; asm("fma.rn.f32x2 %0,%1,%2,%3;" : "=l"(r) : "l"(a), "l"(b), "l"(c)); return r;
}
__device__ __forceinline__ u64 add2(u64 a, u64 b) {
    u64 r; asm("add.rn.f32x2 %0,%1,%2;" : "=l"(r) : "l"(a), "l"(b)); return r;
}
__device__ __forceinline__ u64 mul2(u64 a, u64 b) {
    u64 r; asm("mul.rn.f32x2 %0,%1,%2;" : "=l"(r) : "l"(a), "l"(b)); return r;
}
__device__ __forceinline__ float ex2f(float x) {
    float r; asm("ex2.approx.ftz.f32 %0,%1;" : "=f"(r) : "f"(x)); return r;
}

// ======================================================================
// 1x1 conv (GEMM): out[b][c_off+c][p] = bias[c] + sum_ic w[c][ic]*x[b][ic][p]
// PT=32 pixels/block -> 256 blocks for grid balance.
// ======================================================================
template<int OC, bool QSCALE>
__global__ __launch_bounds__(128)
void conv1x1_kernel(const float* __restrict__ x, const float* __restrict__ w,
                    const float* __restrict__ bias, float* __restrict__ out,
                    int out_bstride, int c_off)
{
    constexpr int PT = 32;            // pixels per block
    extern __shared__ float sm[];
    float* wst = sm;                  // [64][OC] transposed weights
    float* xs  = sm + 64 * OC;        // [64][PT]

    const int tid = threadIdx.x;
    const int pt  = blockIdx.x;
    const int b   = blockIdx.y;
    const int pbase = pt * PT;

    for (int i = tid; i < OC * 64; i += 128) {
        int oc = i >> 6, ic = i & 63;
        wst[ic * OC + oc] = w[i];
    }
    for (int i = tid; i < 64 * PT; i += 128) {
        int ic = i / PT, pp = i - ic * PT;
        xs[i] = x[(b * 64 + ic) * HW + pbase + pp];
    }
    __syncthreads();

    constexpr int CG = OC / 8;
    constexpr int NM = CG * (PT / 2);
    for (int mIdx = tid; mIdx < NM; mIdx += 128) {
        int cg = mIdx / (PT / 2);
        int pg = mIdx - cg * (PT / 2);
        u64 acc[8];
        #pragma unroll
        for (int i = 0; i < 8; ++i) acc[i] = 0ull;

        #pragma unroll 8
        for (int ic = 0; ic < 64; ++ic) {
            const ulonglong2* wp = (const ulonglong2*)(wst + ic * OC + cg * 8);
            ulonglong2 w0 = wp[0], w1 = wp[1];
            float2 xv = *(const float2*)(xs + ic * PT + pg * 2);
            u64 x0 = pk2(xv.x, xv.x), x1 = pk2(xv.y, xv.y);
            acc[0] = fma2(x0, w0.x, acc[0]); acc[1] = fma2(x0, w0.y, acc[1]);
            acc[2] = fma2(x0, w1.x, acc[2]); acc[3] = fma2(x0, w1.y, acc[3]);
            acc[4] = fma2(x1, w0.x, acc[4]); acc[5] = fma2(x1, w0.y, acc[5]);
            acc[6] = fma2(x1, w1.x, acc[6]); acc[7] = fma2(x1, w1.y, acc[7]);
        }

        const int cbase = cg * 8;
        #pragma unroll
        for (int cc = 0; cc < 4; ++cc) {
            int c0 = cbase + 2 * cc;
            float b0 = bias[c0], b1 = bias[c0 + 1];
            float2 f0 = upk2(acc[cc]);       // pixel0 channels c0,c0+1
            float2 f1 = upk2(acc[cc + 4]);   // pixel1
            float v00 = f0.x + b0, v01 = f0.y + b1;
            float v10 = f1.x + b0, v11 = f1.y + b1;
            if (QSCALE && c0 < 64) {         // q channels get dkh^-0.5
                const float S = 0.35355339059327373f;
                v00 *= S; v01 *= S; v10 *= S; v11 *= S;
            }
            size_t base = (size_t)b * out_bstride + (size_t)(c_off + c0) * HW
                        + pbase + pg * 2;
            out[base]          = v00;
            out[base + HW]     = v01;
            out[base + 1]      = v10;
            out[base + HW + 1] = v11;
        }
    }
}

// ======================================================================
// Fused attention: per (b,head), 256 queries/block (grid 4x64 = 256 blocks,
// exactly one wave at 2 blocks/SM). Logits in log2 domain: q pre-scaled by
// log2e (the rel tables are q-dot-products so they inherit the scale), and
// exp is a bare ex2.approx.
// ======================================================================
__global__ __launch_bounds__(256, 2)
void attn_kernel(const float* __restrict__ relw_g, const float* __restrict__ relh_g)
{
    extern __shared__ float sm[];
    float* ks  = sm;                 // [8][1024] d-major (key pairs contiguous)
    float* vs  = sm + 8192;          // [1024][8] key-major (d pairs contiguous)
    float* rws = sm + 16384;         // [63][8]
    float* rhs = sm + 16384 + 512;   // [63][8]

    const int tid  = threadIdx.x;
    const int bh   = blockIdx.y;
    const int b    = bh >> 3;
    const int head = bh & 7;

    const float* kg = g_qkv + (size_t)(b * 192 + 64 + head * 8) * HW;
    const float* vg = kg + 64 * HW;

    for (int i = tid; i < 2048; i += 256)
        ((float4*)ks)[i] = ((const float4*)kg)[i];
    for (int i = tid; i < 2048; i += 256) {
        int d = i >> 8; int j4 = (i & 255) << 2;
        float4 v = ((const float4*)(vg + d * HW))[i & 255];
        vs[(j4 + 0) * 8 + d] = v.x;
        vs[(j4 + 1) * 8 + d] = v.y;
        vs[(j4 + 2) * 8 + d] = v.z;
        vs[(j4 + 3) * 8 + d] = v.w;
    }
    for (int i = tid; i < 504; i += 256) { rws[i] = relw_g[i]; rhs[i] = relh_g[i]; }
    __syncthreads();

    const int p  = blockIdx.x * 256 + tid;   // query pixel
    const int hq = p >> 5, wq = p & 31;
    const float LOG2E = 1.4426950408889634f;

    const float* qg = g_qkv + (size_t)(b * 192 + head * 8) * HW + p;
    float q[8];
    #pragma unroll
    for (int d = 0; d < 8; ++d) q[d] = qg[d * HW] * LOG2E;
    u64 qd[8];
    #pragma unroll
    for (int d = 0; d < 8; ++d) qd[d] = pk2(q[d], q[d]);

    // rel-width table for reachable offsets, packed in registers
    u64 rw[16];
    #pragma unroll
    for (int e = 0; e < 16; ++e) {
        const float* r0 = rws + (2 * e - wq + 31) * 8;
        float a0 = 0.f, a1 = 0.f;
        #pragma unroll
        for (int d = 0; d < 8; ++d) { a0 += q[d] * r0[d]; a1 += q[d] * r0[8 + d]; }
        rw[e] = pk2(a0, a1);
    }
    // rel-height table (dynamic index in main loop -> local mem, 1 LDL / 32 keys)
    float rh[32];
    for (int e = 0; e < 32; ++e) {
        const float* r0 = rhs + (e - hq + 31) * 8;
        float a = 0.f;
        #pragma unroll
        for (int d = 0; d < 8; ++d) a += q[d] * r0[d];
        rh[e] = a;
    }

    float m = -CUDART_INF_F, s = 0.f;
    u64 o[4] = {0ull, 0ull, 0ull, 0ull};

    for (int h2 = 0; h2 < 32; ++h2) {
        float rhv = rh[h2];
        u64 rh2 = pk2(rhv, rhv);
        #pragma unroll
        for (int g = 0; g < 8; ++g) {          // 4 keys per iteration
            int j = h2 * 32 + g * 4;
            u64 l01 = add2(rh2, rw[2 * g]);
            u64 l23 = add2(rh2, rw[2 * g + 1]);
            #pragma unroll
            for (int d = 0; d < 8; ++d) {
                ulonglong2 kk = *(const ulonglong2*)(ks + d * HW + j);
                l01 = fma2(qd[d], kk.x, l01);
                l23 = fma2(qd[d], kk.y, l23);
            }
            float2 f01 = upk2(l01), f23 = upk2(l23);
            float mx = fmaxf(fmaxf(f01.x, f01.y), fmaxf(f23.x, f23.y));
            if (mx > m) {
                float c = ex2f(m - mx);
                s *= c;
                u64 c2 = pk2(c, c);
                o[0] = mul2(o[0], c2); o[1] = mul2(o[1], c2);
                o[2] = mul2(o[2], c2); o[3] = mul2(o[3], c2);
                m = mx;
            }
            float p0 = ex2f(f01.x - m);
            float p1 = ex2f(f01.y - m);
            float p2 = ex2f(f23.x - m);
            float p3 = ex2f(f23.y - m);
            s += (p0 + p1) + (p2 + p3);

            const ulonglong2* vp = (const ulonglong2*)(vs + j * 8);
            ulonglong2 va, vb;
            u64 pd;
            pd = pk2(p0, p0); va = vp[0]; vb = vp[1];
            o[0] = fma2(pd, va.x, o[0]); o[1] = fma2(pd, va.y, o[1]);
            o[2] = fma2(pd, vb.x, o[2]); o[3] = fma2(pd, vb.y, o[3]);
            pd = pk2(p1, p1); va = vp[2]; vb = vp[3];
            o[0] = fma2(pd, va.x, o[0]); o[1] = fma2(pd, va.y, o[1]);
            o[2] = fma2(pd, vb.x, o[2]); o[3] = fma2(pd, vb.y, o[3]);
            pd = pk2(p2, p2); va = vp[4]; vb = vp[5];
            o[0] = fma2(pd, va.x, o[0]); o[1] = fma2(pd, va.y, o[1]);
            o[2] = fma2(pd, vb.x, o[2]); o[3] = fma2(pd, vb.y, o[3]);
            pd = pk2(p3, p3); va = vp[6]; vb = vp[7];
            o[0] = fma2(pd, va.x, o[0]); o[1] = fma2(pd, va.y, o[1]);
            o[2] = fma2(pd, vb.x, o[2]); o[3] = fma2(pd, vb.y, o[3]);
        }
    }

    float inv = 1.f / s;
    float* og = g_attn + (size_t)(b * 64 + head * 8) * HW + p;
    #pragma unroll
    for (int e = 0; e < 4; ++e) {
        float2 f = upk2(o[e]);
        og[(2 * e)     * HW] = f.x * inv;
        og[(2 * e + 1) * HW] = f.y * inv;
    }
}

// ======================================================================
// 3x3 conv, pad 1: 512 blocks (8 row-bands of 4 x 8 oc-groups of 8 x 8 b),
// 128 threads. Thread = one pixel, 8 output channels in 4 f32x2 accumulators.
// ======================================================================
__global__ __launch_bounds__(128)
void conv3x3_kernel(const float* __restrict__ x, const float* __restrict__ w,
                    const float* __restrict__ bias, float* __restrict__ out)
{
    __shared__ float xs[8][6][34];                  // ic-chunk x (4 rows+halo) x (cols+halo)
    __shared__ __align__(16) float wst[8][9][8];    // [ic][k][oc] transposed

    const int tid  = threadIdx.x;
    const int band = blockIdx.x;
    const int ocg  = blockIdx.y;
    const int b    = blockIdx.z;
    const int lr = tid >> 5, lc = tid & 31;
    const int r  = band * 4 + lr;

    u64 acc[4];
    #pragma unroll
    for (int i = 0; i < 4; ++i) acc[i] = 0ull;

    for (int cc8 = 0; cc8 < 64; cc8 += 8) {
        for (int i = tid; i < 8 * 6 * 34; i += 128) {
            int ic = i / 204; int rem = i - ic * 204;
            int rr = rem / 34; int col = rem - rr * 34;
            int gr = band * 4 - 1 + rr; int gc = col - 1;
            float v = 0.f;
            if (gr >= 0 && gr < 32 && gc >= 0 && gc < 32)
                v = x[(b * 64 + cc8 + ic) * HW + gr * 32 + gc];
            xs[ic][rr][col] = v;
        }
        for (int i = tid; i < 8 * 9 * 8; i += 128) {
            int oc = i & 7; int t = i >> 3; int k = t % 9; int ic = t / 9;
            wst[ic][k][oc] = w[((ocg * 8 + oc) * 64 + cc8 + ic) * 9 + k];
        }
        __syncthreads();

        #pragma unroll
        for (int ic = 0; ic < 8; ++ic) {
            float xv[9];
            #pragma unroll
            for (int kr = 0; kr < 3; ++kr)
                #pragma unroll
                for (int kc = 0; kc < 3; ++kc)
                    xv[kr * 3 + kc] = xs[ic][lr + kr][lc + kc];
            #pragma unroll
            for (int k = 0; k < 9; ++k) {
                u64 xd = pk2(xv[k], xv[k]);
                const ulonglong2* wp = (const ulonglong2*)&wst[ic][k][0];
                ulonglong2 wa = wp[0], wb = wp[1];
                acc[0] = fma2(xd, wa.x, acc[0]); acc[1] = fma2(xd, wa.y, acc[1]);
                acc[2] = fma2(xd, wb.x, acc[2]); acc[3] = fma2(xd, wb.y, acc[3]);
            }
        }
        __syncthreads();
    }

    #pragma unroll
    for (int i = 0; i < 4; ++i) {
        int c = ocg * 8 + 2 * i;
        float2 f = upk2(acc[i]);
        size_t base = (size_t)(b * 128 + c) * HW + r * 32 + lc;
        out[base]      = f.x + bias[c];
        out[base + HW] = f.y + bias[c + 1];
    }
}

// ======================================================================
extern "C" void kernel_launch(void* const* d_in, const int* in_sizes, int n_in,
                              void* d_out, int out_size)
{
    const float* x      = (const float*)d_in[0];
    const float* conv_w = (const float*)d_in[1];
    const float* conv_b = (const float*)d_in[2];
    const float* qkv_w  = (const float*)d_in[3];
    const float* qkv_b  = (const float*)d_in[4];
    const float* attn_w = (const float*)d_in[5];
    const float* attn_b = (const float*)d_in[6];
    const float* relw   = (const float*)d_in[7];
    const float* relh   = (const float*)d_in[8];
    float* out = (float*)d_out;

    float *qkv_buf = nullptr, *attn_buf = nullptr;
    cudaGetSymbolAddress((void**)&qkv_buf, g_qkv);
    cudaGetSymbolAddress((void**)&attn_buf, g_attn);

    // one-time infra (host objects only; the captured work is identical
    // every call: two parallel branches joined before return)
    static cudaStream_t s2 = nullptr;
    static cudaEvent_t ev_fork = nullptr, ev_join = nullptr;
    if (s2 == nullptr) {
        cudaStreamCreateWithFlags(&s2, cudaStreamNonBlocking);
        cudaEventCreateWithFlags(&ev_fork, cudaEventDisableTiming);
        cudaEventCreateWithFlags(&ev_join, cudaEventDisableTiming);
        cudaFuncSetAttribute((const void*)conv1x1_kernel<192, true>,
                             cudaFuncAttributeMaxDynamicSharedMemorySize, 57344);
        cudaFuncSetAttribute((const void*)attn_kernel,
                             cudaFuncAttributeMaxDynamicSharedMemorySize, 69632);
    }

    // fork: conv3x3 (independent of attention chain) on side stream
    cudaEventRecord(ev_fork, 0);
    cudaStreamWaitEvent(s2, ev_fork, 0);
    conv3x3_kernel<<<dim3(8, 8, NB), 128, 0, s2>>>(x, conv_w, conv_b, out);
    cudaEventRecord(ev_join, s2);

    // main chain: qkv 1x1 (q scaled) -> fused attention -> output projection
    conv1x1_kernel<192, true><<<dim3(32, NB), 128, 57344>>>(
        x, qkv_w, qkv_b, qkv_buf, 192 * HW, 0);
    attn_kernel<<<dim3(4, 64), 256, 69632>>>(relw, relh);
    conv1x1_kernel<64, false><<<dim3(32, NB), 128, 24576>>>(
        attn_buf, attn_w, attn_b, out, 128 * HW, 64);

    // join
    cudaStreamWaitEvent(0, ev_join, 0);
}